// round 11
// baseline (speedup 1.0000x reference)
#include <cuda_runtime.h>
#include <cooperative_groups.h>

namespace cg = cooperative_groups;

#define T_SEQ 4096
#define IN_DIM 512
#define H_DIM  256
#define G_DIM  1024   // 4*H
#define TILE   32     // handshake granularity (steps)
#define NT     (T_SEQ / TILE)   // 128 tiles
#define G0_POOL 12
#define G1_POOL 12

// ---------------- scratch (no allocation allowed -> device globals) ----------------
__device__ float g_x  [T_SEQ * IN_DIM];        // embedded tokens
__device__ float g_h0 [2][T_SEQ * H_DIM];      // layer-0 hidden seq per dir (step order)
__device__ float g_G0 [2][T_SEQ * G_DIM];      // layer-0 input gates per dir
__device__ float g_G1 [2][T_SEQ * G_DIM];      // layer-1 input gates per dir
__device__ int   g_flag0[2][NT];               // G0 tile completion (counts to 8)
__device__ int   g_flag1[2][NT];               // G1 tile completion (counts to 8)
__device__ int   g_prod [2][8];                // layer-0 rec per-CTA step counters

// ---------------- PTX helpers ----------------
__device__ __forceinline__ unsigned long long ffma2(unsigned long long a,
                                                    unsigned long long b,
                                                    unsigned long long c)
{
    unsigned long long d;
    asm("fma.rn.f32x2 %0, %1, %2, %3;" : "=l"(d) : "l"(a), "l"(b), "l"(c));
    return d;
}
__device__ __forceinline__ unsigned long long packf2(float lo, float hi)
{
    unsigned long long d;
    asm("mov.b64 %0, {%1, %2};" : "=l"(d) : "f"(lo), "f"(hi));
    return d;
}
__device__ __forceinline__ float lof2(unsigned long long v)
{
    float f; asm("{ .reg .b32 hi; mov.b64 {%0, hi}, %1; }" : "=f"(f) : "l"(v)); return f;
}
__device__ __forceinline__ float hif2(unsigned long long v)
{
    float f; asm("{ .reg .b32 lo; mov.b64 {lo, %0}, %1; }" : "=f"(f) : "l"(v)); return f;
}
__device__ __forceinline__ unsigned smem_u32(const void* p)
{
    return (unsigned)__cvta_generic_to_shared(p);
}
__device__ __forceinline__ unsigned mapa_u32(unsigned addr, unsigned rank)
{
    unsigned r;
    asm("mapa.shared::cluster.u32 %0, %1, %2;" : "=r"(r) : "r"(addr), "r"(rank));
    return r;
}
__device__ __forceinline__ void mbar_init(unsigned bar, unsigned cnt)
{
    asm volatile("mbarrier.init.shared::cta.b64 [%0], %1;" :: "r"(bar), "r"(cnt) : "memory");
}
__device__ __forceinline__ void mbar_expect_tx(unsigned bar, unsigned bytes)
{
    asm volatile("mbarrier.arrive.expect_tx.shared::cta.b64 _, [%0], %1;"
                 :: "r"(bar), "r"(bytes) : "memory");
}
__device__ __forceinline__ void mbar_wait(unsigned bar, unsigned parity)
{
    asm volatile(
        "{\n\t"
        ".reg .pred P1;\n\t"
        "LW_%=:\n\t"
        "mbarrier.try_wait.parity.acquire.cta.shared::cta.b64 P1, [%0], %1, 0x989680;\n\t"
        "@P1 bra LD_%=;\n\t"
        "bra LW_%=;\n\t"
        "LD_%=:\n\t"
        "}"
        :: "r"(bar), "r"(parity) : "memory");
}
__device__ __forceinline__ void st_async_f32(unsigned dst, float val, unsigned rbar)
{
    asm volatile(
        "st.async.shared::cluster.mbarrier::complete_tx::bytes.b32 [%0], %1, [%2];"
        :: "r"(dst), "r"(__float_as_uint(val)), "r"(rbar) : "memory");
}

__device__ __forceinline__ float tanh_hw(float x)
{
    float y; asm("tanh.approx.f32 %0, %1;" : "=f"(y) : "f"(x)); return y;
}

// ---- coherent (L2) load: safe for data produced concurrently in this kernel ----
__device__ __forceinline__ float ld_cg(const float* p)
{
    float v;
    asm volatile("ld.global.cg.f32 %0, [%1];" : "=f"(v) : "l"(p) : "memory");
    return v;
}

// global-memory handshake primitives
__device__ __forceinline__ int ld_acq(const int* p)
{
    int v;
    asm volatile("ld.acquire.gpu.global.b32 %0, [%1];" : "=r"(v) : "l"(p) : "memory");
    return v;
}
__device__ __forceinline__ void fence_gpu()
{
    asm volatile("fence.acq_rel.gpu;" ::: "memory");
}
__device__ __forceinline__ void st_rel(int* p, int v)
{
    asm volatile("st.release.gpu.global.b32 [%0], %1;" :: "l"(p), "r"(v) : "memory");
}
__device__ __forceinline__ void red_add_rel(int* p, int v)
{
    asm volatile("red.release.gpu.global.add.s32 [%0], %1;" :: "l"(p), "r"(v) : "memory");
}

// ---------------- embedding gather ----------------
__global__ void embed_kernel(const int* __restrict__ tokens,
                             const float* __restrict__ emb,
                             float* __restrict__ x)
{
    int t = blockIdx.x;
    int tok = tokens[t];
    const float4* src = (const float4*)(emb + (size_t)tok * IN_DIM);
    float4* dst = (float4*)(x + (size_t)t * IN_DIM);
    dst[threadIdx.x] = src[threadIdx.x];
}

// ---------------- flag/counter reset ----------------
__global__ void init_kernel()
{
    int i = threadIdx.x;
    if (i < NT) { g_flag0[0][i] = 0; g_flag0[1][i] = 0;
                  g_flag1[0][i] = 0; g_flag1[1][i] = 0; }
    if (i < 8)  { g_prod[0][i] = 0;  g_prod[1][i] = 0; }
}

// ======================= roles inside the mega kernel =======================

// ---- GEMM worker: computes G[layer] tiles (32 steps x 128 gate-cols) ----
__device__ void worker_role(int layer, int wid,
                            const float* __restrict__ Wf, const float* __restrict__ Wb,
                            const float* __restrict__ b1f, const float* __restrict__ b2f,
                            const float* __restrict__ b1b, const float* __restrict__ b2b,
                            int K)
{
    __shared__ float As[8][33];
    __shared__ float Bs[8][128];

    const int tid = threadIdx.x;
    const int tx = tid & 15, ty = tid >> 4;
    const int arow = tid >> 3, ak = tid & 7;       // A-load coords (32 rows x 8 k)
    const int brow = tid >> 1, bk = (tid & 1) * 4; // B-load coords (128 rows x 8 k)

    const int pool = (layer == 0) ? G0_POOL : G1_POOL;

    for (int item = wid; item < NT * 16; item += pool) {
        const int tile = item >> 4;
        const int sub  = item & 15;
        const int dir  = sub >> 3;
        const int nblk = sub & 7;
        const int m0 = tile * TILE;
        const int n0 = nblk * 128;

        const float* W  = dir ? Wb  : Wf;
        const float* b1 = dir ? b1b : b1f;
        const float* b2 = dir ? b2b : b2f;
        float* C = (layer == 0) ? g_G0[dir] : g_G1[dir];
        int* flag = (layer == 0) ? &g_flag0[dir][tile] : &g_flag1[dir][tile];

        // dependency: layer-1 needs h0[dir] rows m0..m0+31
        if (layer == 1) {
            if (tid == 0) {
                const int target = m0 + TILE;
#pragma unroll
                for (int c = 0; c < 8; c++)
                    while (ld_acq(&g_prod[dir][c]) < target) __nanosleep(512);
            }
            __syncthreads();   // tid0's acquires order all threads' A loads below
        }

        // per-thread A row pointer (layer0 backward reads x reversed)
        const float* Abase = (layer == 0) ? g_x : g_h0[dir];
        int as = m0 + arow;
        if (layer == 0 && dir) as = T_SEQ - 1 - as;
        const float* aptr = Abase + (size_t)as * K;
        const float* wptr = W + (size_t)(n0 + brow) * K;

        float acc[2][8];
#pragma unroll
        for (int i = 0; i < 2; i++)
#pragma unroll
            for (int j = 0; j < 8; j++) acc[i][j] = 0.f;

        for (int k0 = 0; k0 < K; k0 += 8) {
            // layer0 A (= g_x) is immutable during this kernel; h0 needs coherent load
            float av = (layer == 0) ? __ldg(aptr + k0 + ak) : ld_cg(aptr + k0 + ak);
            float4 wv = *(const float4*)(wptr + k0 + bk);   // weights immutable
            __syncthreads();
            As[ak][arow] = av;
            Bs[bk + 0][brow] = wv.x; Bs[bk + 1][brow] = wv.y;
            Bs[bk + 2][brow] = wv.z; Bs[bk + 3][brow] = wv.w;
            __syncthreads();
#pragma unroll
            for (int k = 0; k < 8; k++) {
                float a0 = As[k][ty * 2 + 0];
                float a1 = As[k][ty * 2 + 1];
#pragma unroll
                for (int j = 0; j < 4; j++) {
                    float blo = Bs[k][tx * 4 + j];
                    float bhi = Bs[k][64 + tx * 4 + j];
                    acc[0][j]     = __fmaf_rn(a0, blo, acc[0][j]);
                    acc[1][j]     = __fmaf_rn(a1, blo, acc[1][j]);
                    acc[0][4 + j] = __fmaf_rn(a0, bhi, acc[0][4 + j]);
                    acc[1][4 + j] = __fmaf_rn(a1, bhi, acc[1][4 + j]);
                }
            }
        }

#pragma unroll
        for (int i = 0; i < 2; i++) {
            int m = m0 + ty * 2 + i;
            float* Crow = C + (size_t)m * G_DIM + n0;
#pragma unroll
            for (int j = 0; j < 4; j++) {
                int nlo = tx * 4 + j, nhi = 64 + tx * 4 + j;
                Crow[nlo] = acc[i][j]     + b1[n0 + nlo] + b2[n0 + nlo];
                Crow[nhi] = acc[i][4 + j] + b1[n0 + nhi] + b2[n0 + nhi];
            }
        }

        __syncthreads();   // all C stores issued
        if (tid == 0) { fence_gpu(); red_add_rel(flag, 1); }
    }
}

// ---- LSTM recurrence role (R7 inner loop + tile-gated G + producer publishing) ----
__device__ void rec_role(int dir, int crank,
                         const float* __restrict__ G, const float* __restrict__ Whh,
                         float* __restrict__ outp, int out_stride, int rev_out,
                         float* __restrict__ cell_dst, float* __restrict__ hid_dst,
                         int* prodctr /*null for layer1*/, int* flags)
{
    cg::cluster_group cluster = cg::this_cluster();

    const int tid = threadIdx.x;
    const int w   = tid >> 5;
    const int l   = tid & 31;
    const int r   = l >> 1;
    const int kh  = l & 1;
    const int uiw  = r >> 2;
    const int gate = r & 3;
    const int gu_mine = crank * 32 + w * 4 + uiw;
    const int gu_ew   = crank * 32 + w * 4 + l;

    const float pmul = (gate == 2) ? 1.0f : 0.5f;
    const float padd = (gate == 2) ? 0.0f : 0.5f;

    __shared__ __align__(16) float hbuf[2][H_DIM];
    __shared__ __align__(8) unsigned long long barmem[2];

    const unsigned hbuf_a = smem_u32(&hbuf[0][0]);
    const unsigned bar_a  = smem_u32(&barmem[0]);

    // Whh slice -> registers: 128 floats as 64 f32x2
    unsigned long long w2[64];
    {
        const int grow = gate * H_DIM + gu_mine;
        const float4* wp = (const float4*)(Whh + (size_t)grow * H_DIM + kh * 128);
#pragma unroll
        for (int j = 0; j < 32; j++) {
            float4 v = wp[j];
            w2[2 * j + 0] = packf2(v.x, v.y);
            w2[2 * j + 1] = packf2(v.z, v.w);
        }
    }

    hbuf[0][tid] = 0.f;
    if (tid == 0) {
        mbar_init(bar_a + 0, 1);
        mbar_init(bar_a + 8, 1);
        mbar_expect_tx(bar_a + 0, 1024);   // serves step 2
        mbar_expect_tx(bar_a + 8, 1024);   // serves step 1
    }

    unsigned rhb[8], rbb[8];
#pragma unroll
    for (int rk = 0; rk < 8; rk++) {
        rhb[rk] = mapa_u32(hbuf_a, rk);
        rbb[rk] = mapa_u32(bar_a, rk);
    }

    float cstate = 0.f;

    // wait for tile 0 of G (tid0 spins, CTA-wide ordering via syncthreads)
    if (tid == 0)
        while (ld_acq(&flags[0]) < 8) __nanosleep(256);
    __syncthreads();

    const int growG = gate * H_DIM + gu_mine;
    float g = ld_cg(G + growG);   // coherent load: G produced concurrently

    cluster.sync();

    for (int t = 0; t < T_SEQ; t++) {
        const int buf = t & 1, nb = buf ^ 1;

        if (t > 0) {
            mbar_wait(bar_a + 8 * buf, ((t - 1) >> 1) & 1);
            if (tid == 0) mbar_expect_tx(bar_a + 8 * buf, 1024);  // re-arm for t+2
        }

        // recurrent dot: 128 MACs via 64 FFMA2
        unsigned long long a0 = 0ull, a1 = 0ull, a2 = 0ull, a3 = 0ull;
        const ulonglong2* hp = (const ulonglong2*)&hbuf[buf][kh * 128];
#pragma unroll
        for (int c = 0; c < 4; c++) {
            ulonglong2 hv[8];
#pragma unroll
            for (int q = 0; q < 8; q++) hv[q] = hp[c * 8 + q];
#pragma unroll
            for (int q = 0; q < 4; q++) {
                a0 = ffma2(w2[c * 16 + 4 * q + 0], hv[2 * q].x,     a0);
                a1 = ffma2(w2[c * 16 + 4 * q + 1], hv[2 * q].y,     a1);
                a2 = ffma2(w2[c * 16 + 4 * q + 2], hv[2 * q + 1].x, a2);
                a3 = ffma2(w2[c * 16 + 4 * q + 3], hv[2 * q + 1].y, a3);
            }
        }
        float v = (lof2(a0) + hif2(a0)) + (lof2(a1) + hif2(a1))
                + (lof2(a2) + hif2(a2)) + (lof2(a3) + hif2(a3));
        v += __shfl_xor_sync(0xffffffffu, v, 1);     // combine k-halves

        // per-row activation on all lanes (1 warp-wide MUFU)
        float xg = v + g;
        float yg = tanh_hw(xg * pmul);
        float nh = __fmaf_rn(pmul, yg, padd);

        // gather activated gates (valid lanes 0..3)
        float ih = __shfl_sync(0xffffffffu, nh, (8 * l + 0) & 31);
        float fh = __shfl_sync(0xffffffffu, nh, (8 * l + 2) & 31);
        float gh = __shfl_sync(0xffffffffu, nh, (8 * l + 4) & 31);
        float oh = __shfl_sync(0xffffffffu, nh, (8 * l + 6) & 31);

        cstate = __fmaf_rn(fh, cstate, ih * gh);
        float h = oh * tanh_hw(cstate);

        // broadcast first (critical path)
        if (l < 4 && t < T_SEQ - 1) {
            const unsigned hoff = (unsigned)(nb * (H_DIM * 4) + gu_ew * 4);
            const unsigned boff = (unsigned)(8 * nb);
#pragma unroll
            for (int rk = 0; rk < 8; rk++)
                st_async_f32(rhb[rk] + hoff, h, rbb[rk] + boff);
        }

        if (l < 4) {
            int orow = rev_out ? (T_SEQ - 1 - t) : t;
            outp[(size_t)orow * out_stride + gu_ew] = h;
            if (t == T_SEQ - 1) {
                cell_dst[gu_ew] = cstate;
                hid_dst[gu_ew]  = h;
            }
        }

        // G prefetch for step t+1 (gated at tile boundaries) + producer publish
        const int nt = t + 1;
        if (nt < T_SEQ) {
            if ((nt & (TILE - 1)) == 0) {
                __syncthreads();   // all h0 STGs for steps <= t issued
                if (tid == 0) {
                    if (prodctr) { fence_gpu(); st_rel(prodctr, nt); }
                    const int tile = nt >> 5;
                    while (ld_acq(&flags[tile]) < 8) __nanosleep(256);
                }
                __syncthreads();   // acquire ordering for all threads' G loads
            }
            g = ld_cg(G + (size_t)nt * G_DIM + growG);
        } else if (prodctr) {      // final publish (= T_SEQ) for last G1 tile
            __syncthreads();
            if (tid == 0) { fence_gpu(); st_rel(prodctr, T_SEQ); }
        }
    }
    cluster.sync();
}

// ======================= mega kernel =======================
__global__ __launch_bounds__(256, 1) __cluster_dims__(8, 1, 1)
void mega_kernel(const float* __restrict__ f_Whh0, const float* __restrict__ b_Whh0,
                 const float* __restrict__ f_Whh1, const float* __restrict__ b_Whh1,
                 const float* __restrict__ f_Wih0, const float* __restrict__ b_Wih0,
                 const float* __restrict__ f_Wih1, const float* __restrict__ b_Wih1,
                 const float* __restrict__ f_bih0, const float* __restrict__ f_bhh0,
                 const float* __restrict__ b_bih0, const float* __restrict__ b_bhh0,
                 const float* __restrict__ f_bih1, const float* __restrict__ f_bhh1,
                 const float* __restrict__ b_bih1, const float* __restrict__ b_bhh1,
                 float* __restrict__ out)
{
    const int cid = blockIdx.x;

    if (cid < 32) {
        const int layer = cid >> 4;          // 0..1
        const int dir   = (cid >> 3) & 1;    // 0..1
        const int crank = cid & 7;

        float* cell = out;             // (2,2,256)
        float* hid  = out + 1024;      // (2,2,256)
        float* outs = out + 2048;      // (4096,512)

        if (layer == 0) {
            rec_role(dir, crank,
                     g_G0[dir], dir ? b_Whh0 : f_Whh0,
                     g_h0[dir], H_DIM, 0,
                     cell + dir * 256, hid + dir * 256,
                     &g_prod[dir][crank], g_flag0[dir]);
        } else {
            rec_role(dir, crank,
                     g_G1[dir], dir ? b_Whh1 : f_Whh1,
                     outs + dir * 256, 2 * H_DIM, dir,
                     cell + 512 + dir * 256, hid + 512 + dir * 256,
                     nullptr, g_flag1[dir]);
        }
    } else if (cid < 32 + G0_POOL) {
        worker_role(0, cid - 32, f_Wih0, b_Wih0,
                    f_bih0, f_bhh0, b_bih0, b_bhh0, IN_DIM);
    } else {
        worker_role(1, cid - 32 - G0_POOL, f_Wih1, b_Wih1,
                    f_bih1, f_bhh1, b_bih1, b_bhh1, H_DIM);
    }
}

// ---------------- launch ----------------
extern "C" void kernel_launch(void* const* d_in, const int* in_sizes, int n_in,
                              void* d_out, int out_size)
{
    const int*   tokens  = (const int*)  d_in[0];
    const float* emb     = (const float*)d_in[1];
    const float* f_Wih0  = (const float*)d_in[2];
    const float* f_Whh0  = (const float*)d_in[3];
    const float* f_bih0  = (const float*)d_in[4];
    const float* f_bhh0  = (const float*)d_in[5];
    const float* f_Wih1  = (const float*)d_in[6];
    const float* f_Whh1  = (const float*)d_in[7];
    const float* f_bih1  = (const float*)d_in[8];
    const float* f_bhh1  = (const float*)d_in[9];
    const float* b_Wih0  = (const float*)d_in[10];
    const float* b_Whh0  = (const float*)d_in[11];
    const float* b_bih0  = (const float*)d_in[12];
    const float* b_bhh0  = (const float*)d_in[13];
    const float* b_Wih1  = (const float*)d_in[14];
    const float* b_Whh1  = (const float*)d_in[15];
    const float* b_bih1  = (const float*)d_in[16];
    const float* b_bhh1  = (const float*)d_in[17];
    float* out = (float*)d_out;

    float* x;
    cudaGetSymbolAddress((void**)&x, g_x);

    embed_kernel<<<T_SEQ, IN_DIM / 4>>>(tokens, emb, x);
    init_kernel<<<1, 256>>>();

    mega_kernel<<<32 + G0_POOL + G1_POOL, 256>>>(f_Whh0, b_Whh0, f_Whh1, b_Whh1,
                                                 f_Wih0, b_Wih0, f_Wih1, b_Wih1,
                                                 f_bih0, f_bhh0, b_bih0, b_bhh0,
                                                 f_bih1, f_bhh1, b_bih1, b_bhh1,
                                                 out);
}

// round 12
// speedup vs baseline: 1.9562x; 1.9562x over previous
#include <cuda_runtime.h>
#include <cooperative_groups.h>

namespace cg = cooperative_groups;

#define T_SEQ 4096
#define IN_DIM 512
#define H_DIM  256
#define G_DIM  1024   // 4*H
#define TILE   32     // handshake granularity (steps)
#define NT     (T_SEQ / TILE)   // 128 tiles
#define G0_POOL 24
#define G1_POOL 16

// ---------------- scratch (no allocation allowed -> device globals) ----------------
__device__ float g_x  [T_SEQ * IN_DIM];        // embedded tokens
__device__ float g_h0 [2][T_SEQ * H_DIM];      // layer-0 hidden seq per dir (step order)
__device__ float g_G0 [2][T_SEQ * G_DIM];      // layer-0 input gates per dir
__device__ float g_G1 [2][T_SEQ * G_DIM];      // layer-1 input gates per dir
__device__ int   g_flag0[2][NT];               // G0 tile completion (counts to 8)
__device__ int   g_flag1[2][NT];               // G1 tile completion (counts to 8)
__device__ int   g_prod [2][8];                // layer-0 rec per-CTA step counters

// ---------------- PTX helpers ----------------
__device__ __forceinline__ unsigned long long ffma2(unsigned long long a,
                                                    unsigned long long b,
                                                    unsigned long long c)
{
    unsigned long long d;
    asm("fma.rn.f32x2 %0, %1, %2, %3;" : "=l"(d) : "l"(a), "l"(b), "l"(c));
    return d;
}
__device__ __forceinline__ unsigned long long packf2(float lo, float hi)
{
    unsigned long long d;
    asm("mov.b64 %0, {%1, %2};" : "=l"(d) : "f"(lo), "f"(hi));
    return d;
}
__device__ __forceinline__ float lof2(unsigned long long v)
{
    float f; asm("{ .reg .b32 hi; mov.b64 {%0, hi}, %1; }" : "=f"(f) : "l"(v)); return f;
}
__device__ __forceinline__ float hif2(unsigned long long v)
{
    float f; asm("{ .reg .b32 lo; mov.b64 {lo, %0}, %1; }" : "=f"(f) : "l"(v)); return f;
}
__device__ __forceinline__ unsigned smem_u32(const void* p)
{
    return (unsigned)__cvta_generic_to_shared(p);
}
__device__ __forceinline__ unsigned mapa_u32(unsigned addr, unsigned rank)
{
    unsigned r;
    asm("mapa.shared::cluster.u32 %0, %1, %2;" : "=r"(r) : "r"(addr), "r"(rank));
    return r;
}
__device__ __forceinline__ void mbar_init(unsigned bar, unsigned cnt)
{
    asm volatile("mbarrier.init.shared::cta.b64 [%0], %1;" :: "r"(bar), "r"(cnt) : "memory");
}
__device__ __forceinline__ void mbar_expect_tx(unsigned bar, unsigned bytes)
{
    asm volatile("mbarrier.arrive.expect_tx.shared::cta.b64 _, [%0], %1;"
                 :: "r"(bar), "r"(bytes) : "memory");
}
__device__ __forceinline__ void mbar_wait(unsigned bar, unsigned parity)
{
    asm volatile(
        "{\n\t"
        ".reg .pred P1;\n\t"
        "LW_%=:\n\t"
        "mbarrier.try_wait.parity.acquire.cta.shared::cta.b64 P1, [%0], %1, 0x989680;\n\t"
        "@P1 bra LD_%=;\n\t"
        "bra LW_%=;\n\t"
        "LD_%=:\n\t"
        "}"
        :: "r"(bar), "r"(parity) : "memory");
}
__device__ __forceinline__ void st_async_f32(unsigned dst, float val, unsigned rbar)
{
    asm volatile(
        "st.async.shared::cluster.mbarrier::complete_tx::bytes.b32 [%0], %1, [%2];"
        :: "r"(dst), "r"(__float_as_uint(val)), "r"(rbar) : "memory");
}

__device__ __forceinline__ float tanh_hw(float x)
{
    float y; asm("tanh.approx.f32 %0, %1;" : "=f"(y) : "f"(x)); return y;
}

// ---- coherent (L2) load: safe for data produced concurrently in this kernel ----
__device__ __forceinline__ float ld_cg(const float* p)
{
    float v;
    asm volatile("ld.global.cg.f32 %0, [%1];" : "=f"(v) : "l"(p) : "memory");
    return v;
}

// global-memory handshake primitives
__device__ __forceinline__ int ld_acq(const int* p)
{
    int v;
    asm volatile("ld.acquire.gpu.global.b32 %0, [%1];" : "=r"(v) : "l"(p) : "memory");
    return v;
}
__device__ __forceinline__ void fence_gpu()
{
    asm volatile("fence.acq_rel.gpu;" ::: "memory");
}
__device__ __forceinline__ void st_rel(int* p, int v)
{
    asm volatile("st.release.gpu.global.b32 [%0], %1;" :: "l"(p), "r"(v) : "memory");
}
__device__ __forceinline__ void red_add_rel(int* p, int v)
{
    asm volatile("red.release.gpu.global.add.s32 [%0], %1;" :: "l"(p), "r"(v) : "memory");
}

// ---------------- embedding gather ----------------
__global__ void embed_kernel(const int* __restrict__ tokens,
                             const float* __restrict__ emb,
                             float* __restrict__ x)
{
    int t = blockIdx.x;
    int tok = tokens[t];
    const float4* src = (const float4*)(emb + (size_t)tok * IN_DIM);
    float4* dst = (float4*)(x + (size_t)t * IN_DIM);
    dst[threadIdx.x] = src[threadIdx.x];
}

// ---------------- flag/counter reset ----------------
__global__ void init_kernel()
{
    int i = threadIdx.x;
    if (i < NT) { g_flag0[0][i] = 0; g_flag0[1][i] = 0;
                  g_flag1[0][i] = 0; g_flag1[1][i] = 0; }
    if (i < 8)  { g_prod[0][i] = 0;  g_prod[1][i] = 0; }
}

// ======================= roles inside the mega kernel =======================

// ---- GEMM worker: computes G[layer] tiles (32 steps x 128 gate-cols) ----
__device__ void worker_role(int layer, int wid,
                            const float* __restrict__ Wf, const float* __restrict__ Wb,
                            const float* __restrict__ b1f, const float* __restrict__ b2f,
                            const float* __restrict__ b1b, const float* __restrict__ b2b,
                            int K)
{
    __shared__ float As[8][33];
    __shared__ float Bs[8][128];

    const int tid = threadIdx.x;
    const int tx = tid & 15, ty = tid >> 4;
    const int arow = tid >> 3, ak = tid & 7;       // A-load coords (32 rows x 8 k)
    const int brow = tid >> 1, bk = (tid & 1) * 4; // B-load coords (128 rows x 8 k)

    const int pool = (layer == 0) ? G0_POOL : G1_POOL;

    for (int item = wid; item < NT * 16; item += pool) {
        const int tile = item >> 4;
        const int sub  = item & 15;
        const int dir  = sub >> 3;
        const int nblk = sub & 7;
        const int m0 = tile * TILE;
        const int n0 = nblk * 128;

        const float* W  = dir ? Wb  : Wf;
        const float* b1 = dir ? b1b : b1f;
        const float* b2 = dir ? b2b : b2f;
        float* C = (layer == 0) ? g_G0[dir] : g_G1[dir];
        int* flag = (layer == 0) ? &g_flag0[dir][tile] : &g_flag1[dir][tile];

        // dependency: layer-1 needs h0[dir] rows m0..m0+31
        if (layer == 1) {
            if (tid == 0) {
                const int target = m0 + TILE;
#pragma unroll
                for (int c = 0; c < 8; c++)
                    while (ld_acq(&g_prod[dir][c]) < target) __nanosleep(256);
            }
            __syncthreads();   // tid0's acquires order all threads' A loads below
        }

        // per-thread A row pointer (layer0 backward reads x reversed)
        const float* Abase = (layer == 0) ? g_x : g_h0[dir];
        int as = m0 + arow;
        if (layer == 0 && dir) as = T_SEQ - 1 - as;
        const float* aptr = Abase + (size_t)as * K;
        const float* wptr = W + (size_t)(n0 + brow) * K;

        float acc[2][8];
#pragma unroll
        for (int i = 0; i < 2; i++)
#pragma unroll
            for (int j = 0; j < 8; j++) acc[i][j] = 0.f;

        for (int k0 = 0; k0 < K; k0 += 8) {
            // layer0 A (= g_x) is immutable during this kernel; h0 needs coherent load
            float av = (layer == 0) ? __ldg(aptr + k0 + ak) : ld_cg(aptr + k0 + ak);
            float4 wv = *(const float4*)(wptr + k0 + bk);   // weights immutable
            __syncthreads();
            As[ak][arow] = av;
            Bs[bk + 0][brow] = wv.x; Bs[bk + 1][brow] = wv.y;
            Bs[bk + 2][brow] = wv.z; Bs[bk + 3][brow] = wv.w;
            __syncthreads();
#pragma unroll
            for (int k = 0; k < 8; k++) {
                float a0 = As[k][ty * 2 + 0];
                float a1 = As[k][ty * 2 + 1];
#pragma unroll
                for (int j = 0; j < 4; j++) {
                    float blo = Bs[k][tx * 4 + j];
                    float bhi = Bs[k][64 + tx * 4 + j];
                    acc[0][j]     = __fmaf_rn(a0, blo, acc[0][j]);
                    acc[1][j]     = __fmaf_rn(a1, blo, acc[1][j]);
                    acc[0][4 + j] = __fmaf_rn(a0, bhi, acc[0][4 + j]);
                    acc[1][4 + j] = __fmaf_rn(a1, bhi, acc[1][4 + j]);
                }
            }
        }

#pragma unroll
        for (int i = 0; i < 2; i++) {
            int m = m0 + ty * 2 + i;
            float* Crow = C + (size_t)m * G_DIM + n0;
#pragma unroll
            for (int j = 0; j < 4; j++) {
                int nlo = tx * 4 + j, nhi = 64 + tx * 4 + j;
                Crow[nlo] = acc[i][j]     + b1[n0 + nlo] + b2[n0 + nlo];
                Crow[nhi] = acc[i][4 + j] + b1[n0 + nhi] + b2[n0 + nhi];
            }
        }

        __syncthreads();   // all C stores issued
        if (tid == 0) { fence_gpu(); red_add_rel(flag, 1); }
    }
}

// ---- LSTM recurrence role (R7 inner loop + tile-gated G + producer publishing) ----
__device__ void rec_role(int dir, int crank,
                         const float* __restrict__ G, const float* __restrict__ Whh,
                         float* __restrict__ outp, int out_stride, int rev_out,
                         float* __restrict__ cell_dst, float* __restrict__ hid_dst,
                         int* prodctr /*null for layer1*/, int* flags)
{
    cg::cluster_group cluster = cg::this_cluster();

    const int tid = threadIdx.x;
    const int w   = tid >> 5;
    const int l   = tid & 31;
    const int r   = l >> 1;
    const int kh  = l & 1;
    const int uiw  = r >> 2;
    const int gate = r & 3;
    const int gu_mine = crank * 32 + w * 4 + uiw;
    const int gu_ew   = crank * 32 + w * 4 + l;

    const float pmul = (gate == 2) ? 1.0f : 0.5f;
    const float padd = (gate == 2) ? 0.0f : 0.5f;

    __shared__ __align__(16) float hbuf[2][H_DIM];
    __shared__ __align__(8) unsigned long long barmem[2];

    const unsigned hbuf_a = smem_u32(&hbuf[0][0]);
    const unsigned bar_a  = smem_u32(&barmem[0]);

    // Whh slice -> registers: 128 floats as 64 f32x2
    unsigned long long w2[64];
    {
        const int grow = gate * H_DIM + gu_mine;
        const float4* wp = (const float4*)(Whh + (size_t)grow * H_DIM + kh * 128);
#pragma unroll
        for (int j = 0; j < 32; j++) {
            float4 v = wp[j];
            w2[2 * j + 0] = packf2(v.x, v.y);
            w2[2 * j + 1] = packf2(v.z, v.w);
        }
    }

    hbuf[0][tid] = 0.f;
    if (tid == 0) {
        mbar_init(bar_a + 0, 1);
        mbar_init(bar_a + 8, 1);
        mbar_expect_tx(bar_a + 0, 1024);   // serves step 2
        mbar_expect_tx(bar_a + 8, 1024);   // serves step 1
    }

    unsigned rhb[8], rbb[8];
#pragma unroll
    for (int rk = 0; rk < 8; rk++) {
        rhb[rk] = mapa_u32(hbuf_a, rk);
        rbb[rk] = mapa_u32(bar_a, rk);
    }

    float cstate = 0.f;

    // wait for tile 0 of G (tid0 spins, CTA-wide ordering via syncthreads)
    if (tid == 0)
        while (ld_acq(&flags[0]) < 8) __nanosleep(256);
    __syncthreads();

    const int growG = gate * H_DIM + gu_mine;
    float g = ld_cg(G + growG);   // coherent load: G produced concurrently

    cluster.sync();

    for (int t = 0; t < T_SEQ; t++) {
        const int buf = t & 1, nb = buf ^ 1;

        if (t > 0) {
            mbar_wait(bar_a + 8 * buf, ((t - 1) >> 1) & 1);
            if (tid == 0) mbar_expect_tx(bar_a + 8 * buf, 1024);  // re-arm for t+2
        }

        // recurrent dot: 128 MACs via 64 FFMA2
        unsigned long long a0 = 0ull, a1 = 0ull, a2 = 0ull, a3 = 0ull;
        const ulonglong2* hp = (const ulonglong2*)&hbuf[buf][kh * 128];
#pragma unroll
        for (int c = 0; c < 4; c++) {
            ulonglong2 hv[8];
#pragma unroll
            for (int q = 0; q < 8; q++) hv[q] = hp[c * 8 + q];
#pragma unroll
            for (int q = 0; q < 4; q++) {
                a0 = ffma2(w2[c * 16 + 4 * q + 0], hv[2 * q].x,     a0);
                a1 = ffma2(w2[c * 16 + 4 * q + 1], hv[2 * q].y,     a1);
                a2 = ffma2(w2[c * 16 + 4 * q + 2], hv[2 * q + 1].x, a2);
                a3 = ffma2(w2[c * 16 + 4 * q + 3], hv[2 * q + 1].y, a3);
            }
        }
        float v = (lof2(a0) + hif2(a0)) + (lof2(a1) + hif2(a1))
                + (lof2(a2) + hif2(a2)) + (lof2(a3) + hif2(a3));
        v += __shfl_xor_sync(0xffffffffu, v, 1);     // combine k-halves

        // per-row activation on all lanes (1 warp-wide MUFU)
        float xg = v + g;
        float yg = tanh_hw(xg * pmul);
        float nh = __fmaf_rn(pmul, yg, padd);

        // gather activated gates (valid lanes 0..3)
        float ih = __shfl_sync(0xffffffffu, nh, (8 * l + 0) & 31);
        float fh = __shfl_sync(0xffffffffu, nh, (8 * l + 2) & 31);
        float gh = __shfl_sync(0xffffffffu, nh, (8 * l + 4) & 31);
        float oh = __shfl_sync(0xffffffffu, nh, (8 * l + 6) & 31);

        cstate = __fmaf_rn(fh, cstate, ih * gh);
        float h = oh * tanh_hw(cstate);

        // broadcast first (critical path)
        if (l < 4 && t < T_SEQ - 1) {
            const unsigned hoff = (unsigned)(nb * (H_DIM * 4) + gu_ew * 4);
            const unsigned boff = (unsigned)(8 * nb);
#pragma unroll
            for (int rk = 0; rk < 8; rk++)
                st_async_f32(rhb[rk] + hoff, h, rbb[rk] + boff);
        }

        if (l < 4) {
            int orow = rev_out ? (T_SEQ - 1 - t) : t;
            outp[(size_t)orow * out_stride + gu_ew] = h;
            if (t == T_SEQ - 1) {
                cell_dst[gu_ew] = cstate;
                hid_dst[gu_ew]  = h;
            }
        }

        // G prefetch for step t+1 (gated at tile boundaries) + producer publish
        const int nt = t + 1;
        if (nt < T_SEQ) {
            if ((nt & (TILE - 1)) == 0) {
                __syncthreads();   // all h0 STGs for steps <= t issued
                if (tid == 0) {
                    if (prodctr) { fence_gpu(); st_rel(prodctr, nt); }
                    const int tile = nt >> 5;
                    while (ld_acq(&flags[tile]) < 8) __nanosleep(256);
                }
                __syncthreads();   // acquire ordering for all threads' G loads
            }
            g = ld_cg(G + (size_t)nt * G_DIM + growG);
        } else if (prodctr) {      // final publish (= T_SEQ) for last G1 tile
            __syncthreads();
            if (tid == 0) { fence_gpu(); st_rel(prodctr, T_SEQ); }
        }
    }
    cluster.sync();
}

// ======================= mega kernel =======================
__global__ __launch_bounds__(256, 1) __cluster_dims__(8, 1, 1)
void mega_kernel(const float* __restrict__ f_Whh0, const float* __restrict__ b_Whh0,
                 const float* __restrict__ f_Whh1, const float* __restrict__ b_Whh1,
                 const float* __restrict__ f_Wih0, const float* __restrict__ b_Wih0,
                 const float* __restrict__ f_Wih1, const float* __restrict__ b_Wih1,
                 const float* __restrict__ f_bih0, const float* __restrict__ f_bhh0,
                 const float* __restrict__ b_bih0, const float* __restrict__ b_bhh0,
                 const float* __restrict__ f_bih1, const float* __restrict__ f_bhh1,
                 const float* __restrict__ b_bih1, const float* __restrict__ b_bhh1,
                 float* __restrict__ out)
{
    const int cid = blockIdx.x;

    if (cid < 32) {
        const int layer = cid >> 4;          // 0..1
        const int dir   = (cid >> 3) & 1;    // 0..1
        const int crank = cid & 7;

        float* cell = out;             // (2,2,256)
        float* hid  = out + 1024;      // (2,2,256)
        float* outs = out + 2048;      // (4096,512)

        if (layer == 0) {
            rec_role(dir, crank,
                     g_G0[dir], dir ? b_Whh0 : f_Whh0,
                     g_h0[dir], H_DIM, 0,
                     cell + dir * 256, hid + dir * 256,
                     &g_prod[dir][crank], g_flag0[dir]);
        } else {
            rec_role(dir, crank,
                     g_G1[dir], dir ? b_Whh1 : f_Whh1,
                     outs + dir * 256, 2 * H_DIM, dir,
                     cell + 512 + dir * 256, hid + 512 + dir * 256,
                     nullptr, g_flag1[dir]);
        }
    } else if (cid < 32 + G0_POOL) {
        worker_role(0, cid - 32, f_Wih0, b_Wih0,
                    f_bih0, f_bhh0, b_bih0, b_bhh0, IN_DIM);
    } else {
        worker_role(1, cid - 32 - G0_POOL, f_Wih1, b_Wih1,
                    f_bih1, f_bhh1, b_bih1, b_bhh1, H_DIM);
    }
}

// ---------------- launch ----------------
extern "C" void kernel_launch(void* const* d_in, const int* in_sizes, int n_in,
                              void* d_out, int out_size)
{
    const int*   tokens  = (const int*)  d_in[0];
    const float* emb     = (const float*)d_in[1];
    const float* f_Wih0  = (const float*)d_in[2];
    const float* f_Whh0  = (const float*)d_in[3];
    const float* f_bih0  = (const float*)d_in[4];
    const float* f_bhh0  = (const float*)d_in[5];
    const float* f_Wih1  = (const float*)d_in[6];
    const float* f_Whh1  = (const float*)d_in[7];
    const float* f_bih1  = (const float*)d_in[8];
    const float* f_bhh1  = (const float*)d_in[9];
    const float* b_Wih0  = (const float*)d_in[10];
    const float* b_Whh0  = (const float*)d_in[11];
    const float* b_bih0  = (const float*)d_in[12];
    const float* b_bhh0  = (const float*)d_in[13];
    const float* b_Wih1  = (const float*)d_in[14];
    const float* b_Whh1  = (const float*)d_in[15];
    const float* b_bih1  = (const float*)d_in[16];
    const float* b_bhh1  = (const float*)d_in[17];
    float* out = (float*)d_out;

    float* x;
    cudaGetSymbolAddress((void**)&x, g_x);

    embed_kernel<<<T_SEQ, IN_DIM / 4>>>(tokens, emb, x);
    init_kernel<<<1, 256>>>();

    mega_kernel<<<32 + G0_POOL + G1_POOL, 256>>>(f_Whh0, b_Whh0, f_Whh1, b_Whh1,
                                                 f_Wih0, b_Wih0, f_Wih1, b_Wih1,
                                                 f_bih0, f_bhh0, b_bih0, b_bhh0,
                                                 f_bih1, f_bhh1, b_bih1, b_bhh1,
                                                 out);
}